// round 1
// baseline (speedup 1.0000x reference)
#include <cuda_runtime.h>
#include <math.h>

#define B_   16
#define N_   2048
#define DIN  2
#define U_   64
#define F_   66        // concat feature dim
#define FP   68        // padded feature stride (16B aligned rows)
#define E_   32768
#define NTOT (B_*N_)

// ---------------- scratch (static __device__, no allocation) ----------------
static __device__ float g_x [B_*N_*FP];   // concat features  (b,n,f)
static __device__ float g_x1[B_*N_*FP];   // support spmm result
static __device__ float g_x2[B_*N_*FP];   // adp gemm result
static __device__ float g_s2[NTOT*U_];    // r * hx  (state for 2nd gconv)
static __device__ float g_u [NTOT*U_];    // update gate
static __device__ int   g_cnt[N_];        // histogram / scatter cursor
static __device__ int   g_off[N_ + 1];    // CSR row offsets
static __device__ int   g_ccol[E_];
static __device__ float g_cval[E_];

// ---------------- CSR build ----------------
__global__ void k_zero_cnt() {
    int t = blockIdx.x * blockDim.x + threadIdx.x;
    if (t < N_) g_cnt[t] = 0;
}

__global__ void k_hist(const int* __restrict__ rows) {
    int e = blockIdx.x * blockDim.x + threadIdx.x;
    if (e < E_) atomicAdd(&g_cnt[rows[e]], 1);
}

__global__ __launch_bounds__(1024) void k_scan() {
    __shared__ int sa[N_], sb[N_];
    int t = threadIdx.x;                       // 1024 threads
    sa[t]        = g_cnt[t];
    sa[t + 1024] = g_cnt[t + 1024];
    __syncthreads();
    int* src = sa; int* dst = sb;
    for (int d = 1; d < N_; d <<= 1) {
        for (int k = t; k < N_; k += 1024) {
            int v = src[k];
            if (k >= d) v += src[k - d];
            dst[k] = v;
        }
        __syncthreads();
        int* tmp = src; src = dst; dst = tmp;
    }
    // src = inclusive scan
    int e0 = (t == 0) ? 0 : src[t - 1];
    int e1 = src[t + 1023];
    g_off[t] = e0;        g_off[t + 1024] = e1;
    g_cnt[t] = e0;        g_cnt[t + 1024] = e1;   // cursors for scatter
    if (t == 0) g_off[N_] = src[N_ - 1];
}

__global__ void k_scatter(const int* __restrict__ rows, const int* __restrict__ cols,
                          const float* __restrict__ vals) {
    int e = blockIdx.x * blockDim.x + threadIdx.x;
    if (e < E_) {
        int r = rows[e];
        int p = atomicAdd(&g_cnt[r], 1);
        g_ccol[p] = cols[e];
        g_cval[p] = vals[e];
    }
}

// ---------------- build concat features ----------------
// st layout: (b*N + n)*64 + j   (hx has identical layout: b*131072 + n*64 + j)
__global__ void k_build1(const float* __restrict__ in, const float* __restrict__ st) {
    int idx = blockIdx.x * blockDim.x + threadIdx.x;
    if (idx >= B_ * N_ * FP) return;
    int f  = idx % FP;
    int bn = idx / FP;
    int n  = bn & (N_ - 1);
    int b  = bn >> 11;
    float v = 0.f;
    if (f < DIN)      v = in[b * (N_ * DIN) + n * DIN + f];
    else if (f < F_)  v = st[bn * U_ + (f - DIN)];
    g_x[idx] = v;
}

__global__ void k_build2(const float* __restrict__ in) {
    int idx = blockIdx.x * blockDim.x + threadIdx.x;
    if (idx >= B_ * N_ * FP) return;
    int f  = idx % FP;
    int bn = idx / FP;
    int n  = bn & (N_ - 1);
    int b  = bn >> 11;
    float v = 0.f;
    if (f < DIN)      v = in[b * (N_ * DIN) + n * DIN + f];
    else if (f < F_)  v = g_s2[bn * U_ + (f - DIN)];
    g_x[idx] = v;
}

// ---------------- spmm: x1[b,n,f] = sum_{e in row n} val[e] * x[b,col[e],f] ----------------
__global__ __launch_bounds__(128) void k_spmm() {
    int n = blockIdx.x;
    int s = g_off[n], e = g_off[n + 1];
    int tid = threadIdx.x;
    float acc[9];
#pragma unroll
    for (int j = 0; j < 9; j++) acc[j] = 0.f;

    __shared__ int   scol[128];
    __shared__ float sval[128];

    for (int base = s; base < e; base += 128) {
        int cnt = min(128, e - base);
        if (tid < cnt) { scol[tid] = g_ccol[base + tid]; sval[tid] = g_cval[base + tid]; }
        __syncthreads();
        for (int t = 0; t < cnt; t++) {
            int   c = scol[t];
            float v = sval[t];
#pragma unroll
            for (int j = 0; j < 9; j++) {
                int i = tid + j * 128;
                if (i < B_ * F_) {
                    int b = i / F_, f = i - b * F_;
                    acc[j] += v * g_x[(b * N_ + c) * FP + f];
                }
            }
        }
        __syncthreads();
    }
#pragma unroll
    for (int j = 0; j < 9; j++) {
        int i = tid + j * 128;
        if (i < B_ * F_) {
            int b = i / F_, f = i - b * F_;
            g_x1[(b * N_ + n) * FP + f] = acc[j];
        }
    }
}

// ---------------- big batched GEMM: x2[b] = adp[b] (2048x2048) @ x[b] (2048x66) ----------------
// block: 64 rows x 80 cols (66 real), 256 threads, thread tile 4x5, BK=32
__global__ __launch_bounds__(256) void k_gemm(const float* __restrict__ adp) {
    int b  = blockIdx.x >> 5;
    int m0 = (blockIdx.x & 31) << 6;
    const float* A = adp + (size_t)b * N_ * N_;
    const float* X = g_x + b * N_ * FP;

    __shared__ float As[64][36];
    __shared__ float Bs[32][80];

    int tx = threadIdx.x & 15, ty = threadIdx.x >> 4;
    float acc[4][5];
#pragma unroll
    for (int i = 0; i < 4; i++)
#pragma unroll
        for (int j = 0; j < 5; j++) acc[i][j] = 0.f;

    // zero pad columns 68..79 of Bs once (never overwritten afterwards)
    for (int q = threadIdx.x; q < 32 * 12; q += 256) {
        int r = q / 12, c = 68 + (q - (q / 12) * 12);
        Bs[r][c] = 0.f;
    }

    for (int kt = 0; kt < N_; kt += 32) {
        __syncthreads();
        // A tile: 64 x 32  (512 float4)
        for (int q = threadIdx.x; q < 512; q += 256) {
            int r = q >> 3, c4 = q & 7;
            *(float4*)&As[r][c4 * 4] =
                *(const float4*)&A[(size_t)(m0 + r) * N_ + kt + c4 * 4];
        }
        // B tile: 32 x 68  (544 float4)
        for (int q = threadIdx.x; q < 544; q += 256) {
            int r = q / 17, c4 = q - r * 17;
            *(float4*)&Bs[r][c4 * 4] = *(const float4*)&X[(kt + r) * FP + c4 * 4];
        }
        __syncthreads();
#pragma unroll
        for (int k = 0; k < 32; k++) {
            float a[4], bb[5];
#pragma unroll
            for (int i = 0; i < 4; i++) a[i] = As[4 * ty + i][k];
#pragma unroll
            for (int j = 0; j < 5; j++) bb[j] = Bs[k][tx + 16 * j];
#pragma unroll
            for (int i = 0; i < 4; i++)
#pragma unroll
                for (int j = 0; j < 5; j++) acc[i][j] += a[i] * bb[j];
        }
    }
#pragma unroll
    for (int i = 0; i < 4; i++)
#pragma unroll
        for (int j = 0; j < 5; j++) {
            int c = tx + 16 * j;
            if (c < F_)
                g_x2[(b * N_ + m0 + 4 * ty + i) * FP + c] = acc[i][j];
        }
}

// ---------------- output GEMM: out[row,o] = sum_{m,f} x_m[row,f] * W[f*3+m, o] ----------------
// ON = 128 (ru) or 64 (c). block: 64 rows x ON cols, 256 threads, thread 4 x ON/16.
template <int ON, bool IS_RU>
__global__ __launch_bounds__(256) void k_out(const float* __restrict__ W,
                                             const float* __restrict__ hx,
                                             float* __restrict__ dout) {
    const int JN = ON / 16;
    int row0 = blockIdx.x * 64;
    int b  = row0 >> 11;
    int n0 = row0 & (N_ - 1);
    int tx = threadIdx.x & 15, ty = threadIdx.x >> 4;

    __shared__ float As[64][34];
    __shared__ float Ws[33][ON];

    float acc[4][JN];
#pragma unroll
    for (int i = 0; i < 4; i++)
#pragma unroll
        for (int j = 0; j < JN; j++) acc[i][j] = 0.f;

    const float* bufs[3] = { g_x  + (size_t)b * N_ * FP,
                             g_x1 + (size_t)b * N_ * FP,
                             g_x2 + (size_t)b * N_ * FP };

    for (int m = 0; m < 3; m++) {
        const float* Xb = bufs[m];
        for (int f0 = 0; f0 < F_; f0 += 33) {
            __syncthreads();
            for (int q = threadIdx.x; q < 64 * 33; q += 256) {
                int r = q / 33, kk = q - r * 33;
                As[r][kk] = Xb[(n0 + r) * FP + f0 + kk];
            }
            for (int q = threadIdx.x; q < 33 * (ON / 4); q += 256) {
                int kk = q / (ON / 4), o4 = q - kk * (ON / 4);
                *(float4*)&Ws[kk][o4 * 4] =
                    *(const float4*)&W[((f0 + kk) * 3 + m) * ON + o4 * 4];
            }
            __syncthreads();
#pragma unroll
            for (int k = 0; k < 33; k++) {
                float a[4];
#pragma unroll
                for (int i = 0; i < 4; i++) a[i] = As[4 * ty + i][k];
#pragma unroll
                for (int j = 0; j < JN; j++) {
                    float w = Ws[k][tx + 16 * j];
#pragma unroll
                    for (int i = 0; i < 4; i++) acc[i][j] += a[i] * w;
                }
            }
        }
    }

#pragma unroll
    for (int i = 0; i < 4; i++) {
        int n   = n0 + 4 * ty + i;
        int bn  = b * N_ + n;
#pragma unroll
        for (int j = 0; j < JN; j++) {
            int o = tx + 16 * j;
            if (IS_RU) {
                float v = 1.f / (1.f + expf(-acc[i][j]));
                if (o < U_) g_s2[bn * U_ + o] = v * hx[bn * U_ + o];   // r * hx
                else        g_u [bn * U_ + (o - U_)] = v;              // u
            } else {
                float cv = tanhf(acc[i][j]);
                int idx = bn * U_ + o;
                float u = g_u[idx], h = hx[idx];
                dout[idx] = u * h + (1.f - u) * cv;
            }
        }
    }
}

// ---------------- launch ----------------
extern "C" void kernel_launch(void* const* d_in, const int* in_sizes, int n_in,
                              void* d_out, int out_size) {
    const float* inputs = (const float*)d_in[0];
    const float* hx     = (const float*)d_in[1];
    const float* adp    = (const float*)d_in[2];
    const int*   rows   = (const int*)d_in[3];
    const int*   cols   = (const int*)d_in[4];
    const float* vals   = (const float*)d_in[5];
    const float* W_ru   = (const float*)d_in[6];
    const float* W_c    = (const float*)d_in[7];
    float* out = (float*)d_out;

    (void)in_sizes; (void)n_in; (void)out_size;

    const int nbuild = (B_ * N_ * FP + 255) / 256;

    // CSR of the support matrix (depends only on inputs; rebuilt every call)
    k_zero_cnt<<<(N_ + 255) / 256, 256>>>();
    k_hist   <<<E_ / 256, 256>>>(rows);
    k_scan   <<<1, 1024>>>();
    k_scatter<<<E_ / 256, 256>>>(rows, cols, vals);

    // ---- gconv #1 : gates r,u ----
    k_build1<<<nbuild, 256>>>(inputs, hx);
    k_spmm  <<<N_, 128>>>();
    k_gemm  <<<512, 256>>>(adp);
    k_out<128, true><<<NTOT / 64, 256>>>(W_ru, hx, out);

    // ---- gconv #2 : candidate c, final output ----
    k_build2<<<nbuild, 256>>>(inputs);
    k_spmm  <<<N_, 128>>>();
    k_gemm  <<<512, 256>>>(adp);
    k_out<64, false><<<NTOT / 64, 256>>>(W_c, hx, out);
}

// round 3
// speedup vs baseline: 2.7113x; 2.7113x over previous
#include <cuda_runtime.h>
#include <cuda_bf16.h>
#include <math.h>
#include <cstdint>

#define B_   16
#define N_   2048
#define DIN  2
#define U_   64
#define F_   66        // concat feature dim
#define FP   68        // padded feature stride
#define E_   32768
#define NTOT (B_*N_)
#define NB   80        // padded N for tensor GEMM (warp grid 4x2, warp tile 32x40)

__device__ __forceinline__ uint32_t smem_to_u32(const void* p) {
    uint32_t a;
    asm("{ .reg .u64 t; cvta.to.shared.u64 t, %1; cvt.u32.u64 %0, t; }" : "=r"(a) : "l"(p));
    return a;
}
__device__ __forceinline__ uint32_t pack_bf16x2(float lo, float hi) {
    uint32_t r;
    asm("cvt.rn.bf16x2.f32 %0, %1, %2;" : "=r"(r) : "f"(hi), "f"(lo));
    return r;
}
__device__ __forceinline__ void ldmatrix_x4(uint32_t* r, uint32_t addr) {
    asm volatile("ldmatrix.sync.aligned.m8n8.x4.shared.b16 {%0,%1,%2,%3}, [%4];"
        : "=r"(r[0]), "=r"(r[1]), "=r"(r[2]), "=r"(r[3]) : "r"(addr));
}
__device__ __forceinline__ void ldmatrix_x2(uint32_t* r, uint32_t addr) {
    asm volatile("ldmatrix.sync.aligned.m8n8.x2.shared.b16 {%0,%1}, [%2];"
        : "=r"(r[0]), "=r"(r[1]) : "r"(addr));
}
__device__ __forceinline__ void mma_bf16(float* c, const uint32_t* a, const uint32_t* b) {
    asm volatile("mma.sync.aligned.m16n8k16.row.col.f32.bf16.bf16.f32 "
        "{%0,%1,%2,%3}, {%4,%5,%6,%7}, {%8,%9}, {%0,%1,%2,%3};"
        : "+f"(c[0]), "+f"(c[1]), "+f"(c[2]), "+f"(c[3])
        : "r"(a[0]), "r"(a[1]), "r"(a[2]), "r"(a[3]), "r"(b[0]), "r"(b[1]));
}

// ================= scratch =================
static __device__ float g_x [B_*N_*FP];
static __device__ float g_x1[B_*N_*FP];
static __device__ float g_x2[B_*N_*FP];
static __device__ float g_s2[NTOT*U_];
static __device__ float g_u [NTOT*U_];
static __device__ __nv_bfloat16 g_xt[B_*NB*N_];   // transposed bf16 features (b, f, m)
static __device__ int   g_cnt[N_];
static __device__ int   g_off[N_ + 1];
static __device__ int   g_ccol[E_];
static __device__ float g_cval[E_];

// ================= CSR build =================
__global__ void k_zero_cnt() {
    int t = blockIdx.x * blockDim.x + threadIdx.x;
    if (t < N_) g_cnt[t] = 0;
}
__global__ void k_hist(const int* __restrict__ rows) {
    int e = blockIdx.x * blockDim.x + threadIdx.x;
    if (e < E_) atomicAdd(&g_cnt[rows[e]], 1);
}
__global__ __launch_bounds__(1024) void k_scan() {
    __shared__ int sa[N_], sb[N_];
    int t = threadIdx.x;
    sa[t] = g_cnt[t];
    sa[t + 1024] = g_cnt[t + 1024];
    __syncthreads();
    int* src = sa; int* dst = sb;
    for (int d = 1; d < N_; d <<= 1) {
        for (int k = t; k < N_; k += 1024) {
            int v = src[k];
            if (k >= d) v += src[k - d];
            dst[k] = v;
        }
        __syncthreads();
        int* tmp = src; src = dst; dst = tmp;
    }
    int e0 = (t == 0) ? 0 : src[t - 1];
    int e1 = src[t + 1023];
    g_off[t] = e0;        g_off[t + 1024] = e1;
    g_cnt[t] = e0;        g_cnt[t + 1024] = e1;
    if (t == 0) g_off[N_] = src[N_ - 1];
}
__global__ void k_scatter(const int* __restrict__ rows, const int* __restrict__ cols,
                          const float* __restrict__ vals) {
    int e = blockIdx.x * blockDim.x + threadIdx.x;
    if (e < E_) {
        int r = rows[e];
        int p = atomicAdd(&g_cnt[r], 1);
        g_ccol[p] = cols[e];
        g_cval[p] = vals[e];
    }
}

// ================= fused build: g_x (fp32) + g_xt (bf16, transposed) =================
template <bool USE_S2>
__global__ __launch_bounds__(256) void k_build_xt(const float* __restrict__ in,
                                                  const float* __restrict__ st) {
    __shared__ float sx[64][69];
    int tid = threadIdx.x;
    int b   = blockIdx.x >> 5;
    int m0  = (blockIdx.x & 31) << 6;
    int bn0 = (b << 11) + m0;

    const float* S = USE_S2 ? g_s2 : st;
    for (int q = tid; q < 64 * U_; q += 256) {
        int r = q >> 6, c = q & 63;
        sx[r][2 + c] = S[(bn0 + r) * U_ + c];
    }
    for (int q = tid; q < 64 * DIN; q += 256) {
        int r = q >> 1, j = q & 1;
        sx[r][j] = in[(b << 12) + (m0 + r) * DIN + j];
    }
    __syncthreads();
    for (int q = tid; q < 64 * FP; q += 256) {
        int r = q / FP, f = q - r * FP;
        g_x[(size_t)(bn0 + r) * FP + f] = (f < F_) ? sx[r][f] : 0.f;
    }
    for (int q = tid; q < NB * 64; q += 256) {
        int f = q >> 6, ml = q & 63;
        float v = (f < F_) ? sx[ml][f] : 0.f;
        g_xt[((size_t)(b * NB + f) << 11) + m0 + ml] = __float2bfloat16(v);
    }
}

// ================= spmm =================
__global__ __launch_bounds__(128) void k_spmm() {
    int n = blockIdx.x;
    int s = g_off[n], e = g_off[n + 1];
    int tid = threadIdx.x;
    float acc[9];
#pragma unroll
    for (int j = 0; j < 9; j++) acc[j] = 0.f;

    __shared__ int   scol[128];
    __shared__ float sval[128];

    for (int base = s; base < e; base += 128) {
        int cnt = min(128, e - base);
        if (tid < cnt) { scol[tid] = g_ccol[base + tid]; sval[tid] = g_cval[base + tid]; }
        __syncthreads();
        for (int t = 0; t < cnt; t++) {
            int   c = scol[t];
            float v = sval[t];
#pragma unroll
            for (int j = 0; j < 9; j++) {
                int i = tid + j * 128;
                if (i < B_ * F_) {
                    int bb = i / F_, f = i - bb * F_;
                    acc[j] += v * g_x[(bb * N_ + c) * FP + f];
                }
            }
        }
        __syncthreads();
    }
#pragma unroll
    for (int j = 0; j < 9; j++) {
        int i = tid + j * 128;
        if (i < B_ * F_) {
            int bb = i / F_, f = i - bb * F_;
            g_x1[(bb * N_ + n) * FP + f] = acc[j];
        }
    }
}

// ================= tensor-core adp GEMM (mma.sync bf16) =================
// per CTA: D[128 x 80pad] = adp_tile[128 x 2048](fp32->bf16 fused) @ XT^T
// 256 threads = 8 warps in 4(M) x 2(N) grid; warp tile 32 x 40; K-tile 32.
// smem row stride 40 bf16 = 80 B -> conflict-free for 16B ldmatrix rows.
#define KT      32
#define TILES   (N_ / KT)
#define ASTRIDE 40
#define BSTRIDE 40

__global__ __launch_bounds__(256) void k_gemm_tc(const float* __restrict__ adp) {
    __shared__ __nv_bfloat16 sA[2][128 * ASTRIDE];
    __shared__ __nv_bfloat16 sB[2][NB * BSTRIDE];

    int tid  = threadIdx.x;
    int lane = tid & 31;
    int wid  = tid >> 5;
    int wm   = wid >> 1, wn = wid & 1;
    int m0w  = wm * 32, n0w = wn * 40;

    int b  = blockIdx.x >> 4;
    int m0 = (blockIdx.x & 15) << 7;
    const float* A = adp + (size_t)b * N_ * N_;
    const __nv_bfloat16* XT = g_xt + ((size_t)b * NB << 11);

    float acc[2][5][4];
#pragma unroll
    for (int mi = 0; mi < 2; mi++)
#pragma unroll
        for (int ni = 0; ni < 5; ni++)
#pragma unroll
            for (int c = 0; c < 4; c++) acc[mi][ni][c] = 0.f;

    uint32_t sAaddr = smem_to_u32(&sA[0][0]);
    uint32_t sBaddr = smem_to_u32(&sB[0][0]);
    const uint32_t sAsz = 128 * ASTRIDE * 2;
    const uint32_t sBsz = NB * BSTRIDE * 2;

    // thread's A-load mapping: 4 float4 per tile (128 rows x 8 float4)
    int ar[4], ac4[4];
#pragma unroll
    for (int i = 0; i < 4; i++) {
        int q = tid + i * 256;
        ar[i]  = q >> 3;
        ac4[i] = q & 7;
    }
    // thread's B-load mapping: up to 2 uint4 (80 rows x 4 uint4)
    int bf0 = tid >> 2, bc0 = tid & 3;               // q = tid
    int bf1 = (256 + tid) >> 2, bc1 = (256 + tid) & 3; // q = 256+tid, only tid<64

    // ---- prologue: stage tile 0 ----
    {
        float4 av[4];
#pragma unroll
        for (int i = 0; i < 4; i++)
            av[i] = *(const float4*)&A[(size_t)(m0 + ar[i]) * N_ + ac4[i] * 4];
        uint4 bv0 = *(const uint4*)&XT[(size_t)(bf0 << 11) + bc0 * 8];
        uint4 bv1;
        if (tid < 64) bv1 = *(const uint4*)&XT[(size_t)(bf1 << 11) + bc1 * 8];
#pragma unroll
        for (int i = 0; i < 4; i++) {
            uint32_t p0 = pack_bf16x2(av[i].x, av[i].y);
            uint32_t p1 = pack_bf16x2(av[i].z, av[i].w);
            uint32_t ad = sAaddr + (uint32_t)(ar[i] * ASTRIDE + ac4[i] * 4) * 2;
            asm volatile("st.shared.v2.b32 [%0], {%1, %2};" :: "r"(ad), "r"(p0), "r"(p1) : "memory");
        }
        uint32_t bd = sBaddr + (uint32_t)(bf0 * BSTRIDE) * 2 + bc0 * 16;
        asm volatile("st.shared.v4.b32 [%0], {%1,%2,%3,%4};"
            :: "r"(bd), "r"(bv0.x), "r"(bv0.y), "r"(bv0.z), "r"(bv0.w) : "memory");
        if (tid < 64) {
            bd = sBaddr + (uint32_t)(bf1 * BSTRIDE) * 2 + bc1 * 16;
            asm volatile("st.shared.v4.b32 [%0], {%1,%2,%3,%4};"
                :: "r"(bd), "r"(bv1.x), "r"(bv1.y), "r"(bv1.z), "r"(bv1.w) : "memory");
        }
    }

    // ---- main loop ----
    for (int t = 0; t < TILES; t++) {
        __syncthreads();
        int s = t & 1;
        bool have_next = (t + 1 < TILES);
        float4 av[4];
        uint4 bv0, bv1;
        if (have_next) {
            int kb = (t + 1) * KT;
#pragma unroll
            for (int i = 0; i < 4; i++)
                av[i] = *(const float4*)&A[(size_t)(m0 + ar[i]) * N_ + kb + ac4[i] * 4];
            bv0 = *(const uint4*)&XT[(size_t)(bf0 << 11) + kb + bc0 * 8];
            if (tid < 64) bv1 = *(const uint4*)&XT[(size_t)(bf1 << 11) + kb + bc1 * 8];
        }

        // compute on stage s
        uint32_t aS = sAaddr + s * sAsz;
        uint32_t bS = sBaddr + s * sBsz;
#pragma unroll
        for (int ks = 0; ks < 2; ks++) {
            uint32_t afr[2][4];
#pragma unroll
            for (int mi = 0; mi < 2; mi++) {
                uint32_t ad = aS + (uint32_t)((m0w + mi * 16 + (lane & 15)) * ASTRIDE
                              + ks * 16 + (lane >> 4) * 8) * 2;
                ldmatrix_x4(afr[mi], ad);
            }
            uint32_t bfr[5][2];
#pragma unroll
            for (int ni = 0; ni < 5; ni++) {
                uint32_t bd = bS + (uint32_t)((n0w + ni * 8 + (lane & 7)) * BSTRIDE
                              + ks * 16 + ((lane >> 3) & 1) * 8) * 2;
                ldmatrix_x2(bfr[ni], bd);
            }
#pragma unroll
            for (int mi = 0; mi < 2; mi++)
#pragma unroll
                for (int ni = 0; ni < 5; ni++)
                    mma_bf16(acc[mi][ni], afr[mi], bfr[ni]);
        }

        // stage tile t+1 into buffer s^1
        if (have_next) {
            uint32_t aD = sAaddr + (s ^ 1) * sAsz;
            uint32_t bD = sBaddr + (s ^ 1) * sBsz;
#pragma unroll
            for (int i = 0; i < 4; i++) {
                uint32_t p0 = pack_bf16x2(av[i].x, av[i].y);
                uint32_t p1 = pack_bf16x2(av[i].z, av[i].w);
                uint32_t ad = aD + (uint32_t)(ar[i] * ASTRIDE + ac4[i] * 4) * 2;
                asm volatile("st.shared.v2.b32 [%0], {%1, %2};" :: "r"(ad), "r"(p0), "r"(p1) : "memory");
            }
            uint32_t bd = bD + (uint32_t)(bf0 * BSTRIDE) * 2 + bc0 * 16;
            asm volatile("st.shared.v4.b32 [%0], {%1,%2,%3,%4};"
                :: "r"(bd), "r"(bv0.x), "r"(bv0.y), "r"(bv0.z), "r"(bv0.w) : "memory");
            if (tid < 64) {
                bd = bD + (uint32_t)(bf1 * BSTRIDE) * 2 + bc1 * 16;
                asm volatile("st.shared.v4.b32 [%0], {%1,%2,%3,%4};"
                    :: "r"(bd), "r"(bv1.x), "r"(bv1.y), "r"(bv1.z), "r"(bv1.w) : "memory");
            }
        }
    }

    // ---- epilogue: write fp32 results ----
#pragma unroll
    for (int mi = 0; mi < 2; mi++) {
#pragma unroll
        for (int ni = 0; ni < 5; ni++) {
            int col = n0w + ni * 8 + (lane & 3) * 2;
            if (col < F_) {
                int r0 = m0 + m0w + mi * 16 + (lane >> 2);
                size_t base0 = ((size_t)(b << 11) + r0) * FP + col;
                *(float2*)&g_x2[base0]            = make_float2(acc[mi][ni][0], acc[mi][ni][1]);
                *(float2*)&g_x2[base0 + 8 * FP]   = make_float2(acc[mi][ni][2], acc[mi][ni][3]);
            }
        }
    }
}

// ================= output GEMM (fp32) =================
template <int ON, bool IS_RU>
__global__ __launch_bounds__(256) void k_out(const float* __restrict__ W,
                                             const float* __restrict__ hx,
                                             float* __restrict__ dout) {
    const int JN = ON / 16;
    int row0 = blockIdx.x * 64;
    int b  = row0 >> 11;
    int n0 = row0 & (N_ - 1);
    int tx = threadIdx.x & 15, ty = threadIdx.x >> 4;

    __shared__ float As[64][34];
    __shared__ float Ws[33][ON];

    float acc[4][JN];
#pragma unroll
    for (int i = 0; i < 4; i++)
#pragma unroll
        for (int j = 0; j < JN; j++) acc[i][j] = 0.f;

    const float* bufs[3] = { g_x  + (size_t)b * N_ * FP,
                             g_x1 + (size_t)b * N_ * FP,
                             g_x2 + (size_t)b * N_ * FP };

    for (int m = 0; m < 3; m++) {
        const float* Xb = bufs[m];
        for (int f0 = 0; f0 < F_; f0 += 33) {
            __syncthreads();
            for (int q = threadIdx.x; q < 64 * 33; q += 256) {
                int r = q / 33, kk = q - r * 33;
                As[r][kk] = Xb[(n0 + r) * FP + f0 + kk];
            }
            for (int q = threadIdx.x; q < 33 * (ON / 4); q += 256) {
                int kk = q / (ON / 4), o4 = q - kk * (ON / 4);
                *(float4*)&Ws[kk][o4 * 4] =
                    *(const float4*)&W[((f0 + kk) * 3 + m) * ON + o4 * 4];
            }
            __syncthreads();
#pragma unroll
            for (int k = 0; k < 33; k++) {
                float a[4];
#pragma unroll
                for (int i = 0; i < 4; i++) a[i] = As[4 * ty + i][k];
#pragma unroll
                for (int j = 0; j < JN; j++) {
                    float w = Ws[k][tx + 16 * j];
#pragma unroll
                    for (int i = 0; i < 4; i++) acc[i][j] += a[i] * w;
                }
            }
        }
    }

#pragma unroll
    for (int i = 0; i < 4; i++) {
        int n   = n0 + 4 * ty + i;
        int bn  = b * N_ + n;
#pragma unroll
        for (int j = 0; j < JN; j++) {
            int o = tx + 16 * j;
            if (IS_RU) {
                float v = 1.f / (1.f + expf(-acc[i][j]));
                if (o < U_) g_s2[bn * U_ + o] = v * hx[bn * U_ + o];
                else        g_u [bn * U_ + (o - U_)] = v;
            } else {
                float cv = tanhf(acc[i][j]);
                int idx = bn * U_ + o;
                float u = g_u[idx], h = hx[idx];
                dout[idx] = u * h + (1.f - u) * cv;
            }
        }
    }
}

// ================= launch =================
extern "C" void kernel_launch(void* const* d_in, const int* in_sizes, int n_in,
                              void* d_out, int out_size) {
    const float* inputs = (const float*)d_in[0];
    const float* hx     = (const float*)d_in[1];
    const float* adp    = (const float*)d_in[2];
    const int*   rows   = (const int*)d_in[3];
    const int*   cols   = (const int*)d_in[4];
    const float* vals   = (const float*)d_in[5];
    const float* W_ru   = (const float*)d_in[6];
    const float* W_c    = (const float*)d_in[7];
    float* out = (float*)d_out;
    (void)in_sizes; (void)n_in; (void)out_size;

    // CSR of the support matrix
    k_zero_cnt<<<(N_ + 255) / 256, 256>>>();
    k_hist   <<<E_ / 256, 256>>>(rows);
    k_scan   <<<1, 1024>>>();
    k_scatter<<<E_ / 256, 256>>>(rows, cols, vals);

    // ---- gconv #1 : gates r,u ----
    k_build_xt<false><<<512, 256>>>(inputs, hx);
    k_gemm_tc<<<256, 256>>>(adp);
    k_spmm<<<N_, 128>>>();
    k_out<128, true><<<NTOT / 64, 256>>>(W_ru, hx, out);

    // ---- gconv #2 : candidate c ----
    k_build_xt<true><<<512, 256>>>(inputs, hx);
    k_gemm_tc<<<256, 256>>>(adp);
    k_spmm<<<N_, 128>>>();
    k_out<64, false><<<NTOT / 64, 256>>>(W_c, hx, out);
}

// round 4
// speedup vs baseline: 3.1783x; 1.1722x over previous
#include <cuda_runtime.h>
#include <cuda_bf16.h>
#include <math.h>
#include <cstdint>

#define B_   16
#define N_   2048
#define DIN  2
#define U_   64
#define F_   66        // concat feature dim
#define FP   68        // padded feature stride
#define E_   32768
#define NTOT (B_*N_)
#define NB   80        // padded N for adp tensor GEMM

__device__ __forceinline__ uint32_t smem_to_u32(const void* p) {
    uint32_t a;
    asm("{ .reg .u64 t; cvta.to.shared.u64 t, %1; cvt.u32.u64 %0, t; }" : "=r"(a) : "l"(p));
    return a;
}
__device__ __forceinline__ uint32_t pack_bf16x2(float lo, float hi) {
    uint32_t r;
    asm("cvt.rn.bf16x2.f32 %0, %1, %2;" : "=r"(r) : "f"(hi), "f"(lo));
    return r;
}
__device__ __forceinline__ uint32_t f2tf32(float v) {
    uint32_t r;
    asm("cvt.rna.tf32.f32 %0, %1;" : "=r"(r) : "f"(v));
    return r;
}
__device__ __forceinline__ void ldmatrix_x4(uint32_t* r, uint32_t addr) {
    asm volatile("ldmatrix.sync.aligned.m8n8.x4.shared.b16 {%0,%1,%2,%3}, [%4];"
        : "=r"(r[0]), "=r"(r[1]), "=r"(r[2]), "=r"(r[3]) : "r"(addr));
}
__device__ __forceinline__ void ldmatrix_x2(uint32_t* r, uint32_t addr) {
    asm volatile("ldmatrix.sync.aligned.m8n8.x2.shared.b16 {%0,%1}, [%2];"
        : "=r"(r[0]), "=r"(r[1]) : "r"(addr));
}
__device__ __forceinline__ void mma_bf16(float* c, const uint32_t* a, const uint32_t* b) {
    asm volatile("mma.sync.aligned.m16n8k16.row.col.f32.bf16.bf16.f32 "
        "{%0,%1,%2,%3}, {%4,%5,%6,%7}, {%8,%9}, {%0,%1,%2,%3};"
        : "+f"(c[0]), "+f"(c[1]), "+f"(c[2]), "+f"(c[3])
        : "r"(a[0]), "r"(a[1]), "r"(a[2]), "r"(a[3]), "r"(b[0]), "r"(b[1]));
}
__device__ __forceinline__ void mma_tf32(float* c, const uint32_t* a, const uint32_t* b) {
    asm volatile("mma.sync.aligned.m16n8k8.row.col.f32.tf32.tf32.f32 "
        "{%0,%1,%2,%3}, {%4,%5,%6,%7}, {%8,%9}, {%0,%1,%2,%3};"
        : "+f"(c[0]), "+f"(c[1]), "+f"(c[2]), "+f"(c[3])
        : "r"(a[0]), "r"(a[1]), "r"(a[2]), "r"(a[3]), "r"(b[0]), "r"(b[1]));
}

// ================= scratch =================
static __device__ float g_x [B_*N_*FP];
static __device__ float g_x1[B_*N_*FP];
static __device__ float g_x2[B_*N_*FP];
static __device__ float g_s2[NTOT*U_];
static __device__ float g_u [NTOT*U_];
static __device__ __nv_bfloat16 g_xt[B_*NB*N_];   // transposed bf16 features
static __device__ uint32_t g_wp_ru[216*128];      // permuted tf32 W_ru (k = m*72+f)
static __device__ uint32_t g_wp_c [216*64];       // permuted tf32 W_c
static __device__ int   g_cnt[N_];
static __device__ int   g_off[N_ + 1];
static __device__ int   g_ccol[E_];
static __device__ float g_cval[E_];

// ================= CSR build =================
__global__ void k_zero_cnt() {
    int t = blockIdx.x * blockDim.x + threadIdx.x;
    if (t < N_) g_cnt[t] = 0;
}
__global__ void k_hist(const int* __restrict__ rows) {
    int e = blockIdx.x * blockDim.x + threadIdx.x;
    if (e < E_) atomicAdd(&g_cnt[rows[e]], 1);
}
__global__ __launch_bounds__(1024) void k_scan() {
    __shared__ int sa[N_], sb[N_];
    int t = threadIdx.x;
    sa[t] = g_cnt[t];
    sa[t + 1024] = g_cnt[t + 1024];
    __syncthreads();
    int* src = sa; int* dst = sb;
    for (int d = 1; d < N_; d <<= 1) {
        for (int k = t; k < N_; k += 1024) {
            int v = src[k];
            if (k >= d) v += src[k - d];
            dst[k] = v;
        }
        __syncthreads();
        int* tmp = src; src = dst; dst = tmp;
    }
    int e0 = (t == 0) ? 0 : src[t - 1];
    int e1 = src[t + 1023];
    g_off[t] = e0;        g_off[t + 1024] = e1;
    g_cnt[t] = e0;        g_cnt[t + 1024] = e1;
    if (t == 0) g_off[N_] = src[N_ - 1];
}
__global__ void k_scatter(const int* __restrict__ rows, const int* __restrict__ cols,
                          const float* __restrict__ vals) {
    int e = blockIdx.x * blockDim.x + threadIdx.x;
    if (e < E_) {
        int r = rows[e];
        int p = atomicAdd(&g_cnt[r], 1);
        g_ccol[p] = cols[e];
        g_cval[p] = vals[e];
    }
}

// ================= W permute + tf32 convert =================
__global__ void k_wperm(const float* __restrict__ W_ru, const float* __restrict__ W_c) {
    int idx = blockIdx.x * blockDim.x + threadIdx.x;
    if (idx < 216 * 128) {
        int kk = idx >> 7, o = idx & 127;
        int m = kk / 72, f = kk - m * 72;
        float v = (f < F_) ? W_ru[(f * 3 + m) * 128 + o] : 0.f;
        g_wp_ru[idx] = f2tf32(v);
    } else {
        int j = idx - 216 * 128;
        if (j < 216 * 64) {
            int kk = j >> 6, o = j & 63;
            int m = kk / 72, f = kk - m * 72;
            float v = (f < F_) ? W_c[(f * 3 + m) * 64 + o] : 0.f;
            g_wp_c[j] = f2tf32(v);
        }
    }
}

// ================= fused build: g_x (fp32) + g_xt (bf16, transposed) =================
template <bool USE_S2>
__global__ __launch_bounds__(256) void k_build_xt(const float* __restrict__ in,
                                                  const float* __restrict__ st) {
    __shared__ float sx[64][69];
    int tid = threadIdx.x;
    int b   = blockIdx.x >> 5;
    int m0  = (blockIdx.x & 31) << 6;
    int bn0 = (b << 11) + m0;

    const float* S = USE_S2 ? g_s2 : st;
    for (int q = tid; q < 64 * U_; q += 256) {
        int r = q >> 6, c = q & 63;
        sx[r][2 + c] = S[(bn0 + r) * U_ + c];
    }
    for (int q = tid; q < 64 * DIN; q += 256) {
        int r = q >> 1, j = q & 1;
        sx[r][j] = in[(b << 12) + (m0 + r) * DIN + j];
    }
    __syncthreads();
    for (int q = tid; q < 64 * FP; q += 256) {
        int r = q / FP, f = q - r * FP;
        g_x[(size_t)(bn0 + r) * FP + f] = (f < F_) ? sx[r][f] : 0.f;
    }
    for (int q = tid; q < NB * 64; q += 256) {
        int f = q >> 6, ml = q & 63;
        float v = (f < F_) ? sx[ml][f] : 0.f;
        g_xt[((size_t)(b * NB + f) << 11) + m0 + ml] = __float2bfloat16(v);
    }
}

// ================= spmm =================
__global__ __launch_bounds__(128) void k_spmm() {
    int n = blockIdx.x;
    int s = g_off[n], e = g_off[n + 1];
    int tid = threadIdx.x;
    float acc[9];
#pragma unroll
    for (int j = 0; j < 9; j++) acc[j] = 0.f;

    __shared__ int   scol[128];
    __shared__ float sval[128];

    for (int base = s; base < e; base += 128) {
        int cnt = min(128, e - base);
        if (tid < cnt) { scol[tid] = g_ccol[base + tid]; sval[tid] = g_cval[base + tid]; }
        __syncthreads();
        for (int t = 0; t < cnt; t++) {
            int   c = scol[t];
            float v = sval[t];
#pragma unroll
            for (int j = 0; j < 9; j++) {
                int i = tid + j * 128;
                if (i < B_ * F_) {
                    int bb = i / F_, f = i - bb * F_;
                    acc[j] += v * g_x[(bb * N_ + c) * FP + f];
                }
            }
        }
        __syncthreads();
    }
#pragma unroll
    for (int j = 0; j < 9; j++) {
        int i = tid + j * 128;
        if (i < B_ * F_) {
            int bb = i / F_, f = i - bb * F_;
            g_x1[(bb * N_ + n) * FP + f] = acc[j];
        }
    }
}

// ================= tensor-core adp GEMM (mma.sync bf16) =================
#define KT      32
#define TILES   (N_ / KT)
#define ASTRIDE 40
#define BSTRIDE 40

__global__ __launch_bounds__(256) void k_gemm_tc(const float* __restrict__ adp) {
    __shared__ __nv_bfloat16 sA[2][128 * ASTRIDE];
    __shared__ __nv_bfloat16 sB[2][NB * BSTRIDE];

    int tid  = threadIdx.x;
    int lane = tid & 31;
    int wid  = tid >> 5;
    int wm   = wid >> 1, wn = wid & 1;
    int m0w  = wm * 32, n0w = wn * 40;

    int b  = blockIdx.x >> 4;
    int m0 = (blockIdx.x & 15) << 7;
    const float* A = adp + (size_t)b * N_ * N_;
    const __nv_bfloat16* XT = g_xt + ((size_t)b * NB << 11);

    float acc[2][5][4];
#pragma unroll
    for (int mi = 0; mi < 2; mi++)
#pragma unroll
        for (int ni = 0; ni < 5; ni++)
#pragma unroll
            for (int c = 0; c < 4; c++) acc[mi][ni][c] = 0.f;

    uint32_t sAaddr = smem_to_u32(&sA[0][0]);
    uint32_t sBaddr = smem_to_u32(&sB[0][0]);
    const uint32_t sAsz = 128 * ASTRIDE * 2;
    const uint32_t sBsz = NB * BSTRIDE * 2;

    int ar[4], ac4[4];
#pragma unroll
    for (int i = 0; i < 4; i++) {
        int q = tid + i * 256;
        ar[i]  = q >> 3;
        ac4[i] = q & 7;
    }
    int bf0 = tid >> 2, bc0 = tid & 3;
    int bf1 = (256 + tid) >> 2, bc1 = (256 + tid) & 3;

    {
        float4 av[4];
#pragma unroll
        for (int i = 0; i < 4; i++)
            av[i] = *(const float4*)&A[(size_t)(m0 + ar[i]) * N_ + ac4[i] * 4];
        uint4 bv0 = *(const uint4*)&XT[(size_t)(bf0 << 11) + bc0 * 8];
        uint4 bv1;
        if (tid < 64) bv1 = *(const uint4*)&XT[(size_t)(bf1 << 11) + bc1 * 8];
#pragma unroll
        for (int i = 0; i < 4; i++) {
            uint32_t p0 = pack_bf16x2(av[i].x, av[i].y);
            uint32_t p1 = pack_bf16x2(av[i].z, av[i].w);
            uint32_t ad = sAaddr + (uint32_t)(ar[i] * ASTRIDE + ac4[i] * 4) * 2;
            asm volatile("st.shared.v2.b32 [%0], {%1, %2};" :: "r"(ad), "r"(p0), "r"(p1) : "memory");
        }
        uint32_t bd = sBaddr + (uint32_t)(bf0 * BSTRIDE) * 2 + bc0 * 16;
        asm volatile("st.shared.v4.b32 [%0], {%1,%2,%3,%4};"
            :: "r"(bd), "r"(bv0.x), "r"(bv0.y), "r"(bv0.z), "r"(bv0.w) : "memory");
        if (tid < 64) {
            bd = sBaddr + (uint32_t)(bf1 * BSTRIDE) * 2 + bc1 * 16;
            asm volatile("st.shared.v4.b32 [%0], {%1,%2,%3,%4};"
                :: "r"(bd), "r"(bv1.x), "r"(bv1.y), "r"(bv1.z), "r"(bv1.w) : "memory");
        }
    }

    for (int t = 0; t < TILES; t++) {
        __syncthreads();
        int s = t & 1;
        bool have_next = (t + 1 < TILES);
        float4 av[4];
        uint4 bv0, bv1;
        if (have_next) {
            int kb = (t + 1) * KT;
#pragma unroll
            for (int i = 0; i < 4; i++)
                av[i] = *(const float4*)&A[(size_t)(m0 + ar[i]) * N_ + kb + ac4[i] * 4];
            bv0 = *(const uint4*)&XT[(size_t)(bf0 << 11) + kb + bc0 * 8];
            if (tid < 64) bv1 = *(const uint4*)&XT[(size_t)(bf1 << 11) + kb + bc1 * 8];
        }

        uint32_t aS = sAaddr + s * sAsz;
        uint32_t bS = sBaddr + s * sBsz;
#pragma unroll
        for (int ks = 0; ks < 2; ks++) {
            uint32_t afr[2][4];
#pragma unroll
            for (int mi = 0; mi < 2; mi++) {
                uint32_t ad = aS + (uint32_t)((m0w + mi * 16 + (lane & 15)) * ASTRIDE
                              + ks * 16 + (lane >> 4) * 8) * 2;
                ldmatrix_x4(afr[mi], ad);
            }
            uint32_t bfr[5][2];
#pragma unroll
            for (int ni = 0; ni < 5; ni++) {
                uint32_t bd = bS + (uint32_t)((n0w + ni * 8 + (lane & 7)) * BSTRIDE
                              + ks * 16 + ((lane >> 3) & 1) * 8) * 2;
                ldmatrix_x2(bfr[ni], bd);
            }
#pragma unroll
            for (int mi = 0; mi < 2; mi++)
#pragma unroll
                for (int ni = 0; ni < 5; ni++)
                    mma_bf16(acc[mi][ni], afr[mi], bfr[ni]);
        }

        if (have_next) {
            uint32_t aD = sAaddr + (s ^ 1) * sAsz;
            uint32_t bD = sBaddr + (s ^ 1) * sBsz;
#pragma unroll
            for (int i = 0; i < 4; i++) {
                uint32_t p0 = pack_bf16x2(av[i].x, av[i].y);
                uint32_t p1 = pack_bf16x2(av[i].z, av[i].w);
                uint32_t ad = aD + (uint32_t)(ar[i] * ASTRIDE + ac4[i] * 4) * 2;
                asm volatile("st.shared.v2.b32 [%0], {%1, %2};" :: "r"(ad), "r"(p0), "r"(p1) : "memory");
            }
            uint32_t bd = bD + (uint32_t)(bf0 * BSTRIDE) * 2 + bc0 * 16;
            asm volatile("st.shared.v4.b32 [%0], {%1,%2,%3,%4};"
                :: "r"(bd), "r"(bv0.x), "r"(bv0.y), "r"(bv0.z), "r"(bv0.w) : "memory");
            if (tid < 64) {
                bd = bD + (uint32_t)(bf1 * BSTRIDE) * 2 + bc1 * 16;
                asm volatile("st.shared.v4.b32 [%0], {%1,%2,%3,%4};"
                    :: "r"(bd), "r"(bv1.x), "r"(bv1.y), "r"(bv1.z), "r"(bv1.w) : "memory");
            }
        }
    }

#pragma unroll
    for (int mi = 0; mi < 2; mi++) {
#pragma unroll
        for (int ni = 0; ni < 5; ni++) {
            int col = n0w + ni * 8 + (lane & 3) * 2;
            if (col < F_) {
                int r0 = m0 + m0w + mi * 16 + (lane >> 2);
                size_t base0 = ((size_t)(b << 11) + r0) * FP + col;
                *(float2*)&g_x2[base0]            = make_float2(acc[mi][ni][0], acc[mi][ni][1]);
                *(float2*)&g_x2[base0 + 8 * FP]   = make_float2(acc[mi][ni][2], acc[mi][ni][3]);
            }
        }
    }
}

// ================= output GEMM (tf32 tensor cores) =================
// per CTA: 64 rows x ON cols, K = 3 segments x 72 (zero-padded from 66).
// smem: sA 64x76 tf32, sB 72x(ON+4) tf32. 8 warps.
template <int ON, bool IS_RU>
__global__ __launch_bounds__(256) void k_out_tc(const uint32_t* __restrict__ Wp,
                                                const float* __restrict__ hx,
                                                float* __restrict__ dout) {
    extern __shared__ uint32_t sm[];
    const int ASTR = 76;
    const int BSTR = ON + 4;
    uint32_t* sA = sm;                 // 64 x 76
    uint32_t* sB = sm + 64 * ASTR;     // 72 x BSTR

    const int WNW   = ON / 32;         // warps along N
    const int MFRAG = (ON == 128) ? 2 : 1;
    const int WTM   = MFRAG * 16;

    int tid = threadIdx.x, lane = tid & 31, wid = tid >> 5;
    int wn = wid % WNW, wm = wid / WNW;
    int row0 = blockIdx.x * 64;
    int g = lane >> 2, tt = lane & 3;

    // zero A pad cols 66..71 once
    for (int q = tid; q < 64 * 6; q += 256) {
        int r = q / 6, c = 66 + (q - r * 6);
        sA[r * ASTR + c] = 0;
    }

    float acc[MFRAG][4][4];
#pragma unroll
    for (int mi = 0; mi < MFRAG; mi++)
#pragma unroll
        for (int ni = 0; ni < 4; ni++)
#pragma unroll
            for (int c = 0; c < 4; c++) acc[mi][ni][c] = 0.f;

    for (int m = 0; m < 3; m++) {
        const float* Xb = (m == 0) ? g_x : (m == 1) ? g_x1 : g_x2;
        __syncthreads();
        // A: 64 rows x 66 cols -> tf32 smem; 17 tasks/row (16 float4 + 1 float2)
        for (int q = tid; q < 64 * 17; q += 256) {
            int r = q / 17, p = q - r * 17;
            size_t src = (size_t)(row0 + r) * FP;
            uint32_t dst = r * ASTR;
            if (p < 16) {
                float4 v = *(const float4*)&Xb[src + p * 4];
                uint32_t t0 = f2tf32(v.x), t1 = f2tf32(v.y), t2 = f2tf32(v.z), t3 = f2tf32(v.w);
                *(uint4*)&sA[dst + p * 4] = make_uint4(t0, t1, t2, t3);
            } else {
                float2 v = *(const float2*)&Xb[src + 64];
                sA[dst + 64] = f2tf32(v.x);
                sA[dst + 65] = f2tf32(v.y);
            }
        }
        // B: 72 x ON tf32 words
        for (int q = tid; q < 72 * (ON / 4); q += 256) {
            int r = q / (ON / 4), c4 = q - r * (ON / 4);
            uint4 v = *(const uint4*)&Wp[(m * 72 + r) * ON + c4 * 4];
            *(uint4*)&sB[r * BSTR + c4 * 4] = v;
        }
        __syncthreads();
#pragma unroll
        for (int kt = 0; kt < 9; kt++) {
            int k0 = kt * 8;
            uint32_t af[MFRAG][4];
#pragma unroll
            for (int mi = 0; mi < MFRAG; mi++) {
                int r0 = wm * WTM + mi * 16 + g;
                int kc = k0 + tt;
                af[mi][0] = sA[r0 * ASTR + kc];
                af[mi][1] = sA[(r0 + 8) * ASTR + kc];
                af[mi][2] = sA[r0 * ASTR + kc + 4];
                af[mi][3] = sA[(r0 + 8) * ASTR + kc + 4];
            }
            uint32_t bf[4][2];
#pragma unroll
            for (int ni = 0; ni < 4; ni++) {
                int col = wn * 32 + ni * 8 + g;
                int kr = k0 + tt;
                bf[ni][0] = sB[kr * BSTR + col];
                bf[ni][1] = sB[(kr + 4) * BSTR + col];
            }
#pragma unroll
            for (int mi = 0; mi < MFRAG; mi++)
#pragma unroll
                for (int ni = 0; ni < 4; ni++)
                    mma_tf32(acc[mi][ni], af[mi], bf[ni]);
        }
    }

    // epilogue
#pragma unroll
    for (int mi = 0; mi < MFRAG; mi++) {
#pragma unroll
        for (int ni = 0; ni < 4; ni++) {
            int r0  = row0 + wm * WTM + mi * 16 + g;
            int col = wn * 32 + ni * 8 + tt * 2;
#pragma unroll
            for (int h = 0; h < 2; h++) {        // h=0: rows r0; h=1: rows r0+8
                int bn = r0 + h * 8;
#pragma unroll
                for (int cc = 0; cc < 2; cc++) { // col, col+1
                    float v = acc[mi][ni][h * 2 + cc];
                    int o = col + cc;
                    if (IS_RU) {
                        float s = 1.f / (1.f + expf(-v));
                        if (o < U_) g_s2[bn * U_ + o] = s * hx[bn * U_ + o];
                        else        g_u [bn * U_ + (o - U_)] = s;
                    } else {
                        float cv = tanhf(v);
                        int idx = bn * U_ + o;
                        float u = g_u[idx], hh = hx[idx];
                        dout[idx] = u * hh + (1.f - u) * cv;
                    }
                }
            }
        }
    }
}

// ================= launch =================
extern "C" void kernel_launch(void* const* d_in, const int* in_sizes, int n_in,
                              void* d_out, int out_size) {
    const float* inputs = (const float*)d_in[0];
    const float* hx     = (const float*)d_in[1];
    const float* adp    = (const float*)d_in[2];
    const int*   rows   = (const int*)d_in[3];
    const int*   cols   = (const int*)d_in[4];
    const float* vals   = (const float*)d_in[5];
    const float* W_ru   = (const float*)d_in[6];
    const float* W_c    = (const float*)d_in[7];
    float* out = (float*)d_out;
    (void)in_sizes; (void)n_in; (void)out_size;

    const int SMEM_RU = (64 * 76 + 72 * 132) * 4;
    const int SMEM_C  = (64 * 76 + 72 * 68) * 4;
    cudaFuncSetAttribute(k_out_tc<128, true>,  cudaFuncAttributeMaxDynamicSharedMemorySize, SMEM_RU);
    cudaFuncSetAttribute(k_out_tc<64, false>,  cudaFuncAttributeMaxDynamicSharedMemorySize, SMEM_C);

    uint32_t* wp_ru; cudaGetSymbolAddress((void**)&wp_ru, g_wp_ru);
    uint32_t* wp_c;  cudaGetSymbolAddress((void**)&wp_c,  g_wp_c);

    // ordered so k_gemm_tc is the 4th launch (ncu profiling slot)
    k_zero_cnt<<<(N_ + 255) / 256, 256>>>();
    k_hist    <<<E_ / 256, 256>>>(rows);
    k_build_xt<false><<<512, 256>>>(inputs, hx);
    k_gemm_tc <<<256, 256>>>(adp);                         // profiled
    k_scan    <<<1, 1024>>>();
    k_scatter <<<E_ / 256, 256>>>(rows, cols, vals);
    k_wperm   <<<162, 256>>>(W_ru, W_c);
    k_spmm    <<<N_, 128>>>();
    k_out_tc<128, true><<<NTOT / 64, 256, SMEM_RU>>>(wp_ru, hx, out);

    k_build_xt<true><<<512, 256>>>(inputs, hx);
    k_gemm_tc <<<256, 256>>>(adp);
    k_spmm    <<<N_, 128>>>();
    k_out_tc<64, false><<<NTOT / 64, 256, SMEM_C>>>(wp_c, hx, out);
}